// round 13
// baseline (speedup 1.0000x reference)
#include <cuda_runtime.h>
#include <math.h>

#define AT 48
#define SP 4
#define RCRf 5.2f
#define RCAf 3.5f
#define NSHFR 16
#define NSHFA 4
#define NSHFZ 8
#define RADSUB (SP * NSHFR)                 // 64
#define ANGSUB (NSHFA * NSHFZ)              // 32
#define NPAIRS_SP (SP * (SP + 1) / 2)       // 10
#define OUTW (RADSUB + NPAIRS_SP * ANGSUB)  // 384
#define NPCAP 512                           // pair-chunk capacity (n<=32 -> 1 chunk)
#define NT 128
#define PI_F 3.14159265358979f

struct SmemLayout {
    float  shfR[NSHFR], shfA[NSHFA], czv[NSHFZ], szv[NSHFZ];
    float  sEtaR, sEtaA, sZeta;
    // radial neighbors bucketed by species: {d, 0.25*fc}
    int    rcnt[SP];
    float2 rbdf[SP * AT];
    // compacted angular neighbor list (d <= RCA, j != i)
    int    nn;
    float  adx[AT], ady[AT], adz[AT], ad[AT], ard[AT], afc[AT];
    int    asp[AT];
    // chunked pair data + species-pair id + sorted index order
    float4         pdata[NPCAP];   // {cos, sin, 2*fc1*fc2, dmean}
    unsigned char  ppx[NPCAP];
    unsigned short ord[NPCAP];
    int    acnt[NPAIRS_SP], abase[NPAIRS_SP], afill[NPAIRS_SP];
};

__device__ __forceinline__ float ang_accum(
    const SmemLayout* sm, float accv, int pidx,
    float cz, float sz, float sh, float etaA, float zeta, bool z32)
{
    const int pb = sm->abase[pidx];
    const int pe = pb + sm->acnt[pidx];
    for (int q = pb; q < pe; q++) {
        float4 pd = sm->pdata[sm->ord[q]];   // broadcast LDS.128
        float cd   = pd.x * cz + pd.y * sz;  // cos(theta - ShfZ[z])
        float base = 0.5f + 0.5f * cd;
        float f1;
        if (z32) {
            float x = base;                  // base^32: even power, no clamp
            x *= x; x *= x; x *= x; x *= x; x *= x;
            f1 = x;
        } else {
            f1 = __powf(fmaxf(base, 0.0f), zeta);
        }
        float t = pd.w - sh;
        accv = fmaf(f1, pd.z * __expf(-etaA * t * t), accv);
    }
    return accv;
}

__global__ __launch_bounds__(NT, 16) void aev_kernel(
    const float* __restrict__ coords,   // (M, A, 3)
    const float* __restrict__ gEtaR,
    const float* __restrict__ gShfR,
    const float* __restrict__ gEtaA,
    const float* __restrict__ gZeta,
    const float* __restrict__ gShfA,
    const float* __restrict__ gShfZ,
    const int*   __restrict__ species,  // (M, A)
    float* __restrict__ out)            // (M, A, 384)
{
    const int i = blockIdx.x;
    const int m = blockIdx.y;
    const int tid = threadIdx.x;

    __shared__ SmemLayout sm;

    // ---- phase 0: params + counter init (barrier below is load-bearing) ----
    if (tid < NSHFR) sm.shfR[tid] = gShfR[tid];
    if (tid < NSHFA) sm.shfA[tid] = gShfA[tid];
    if (tid < NSHFZ) __sincosf(gShfZ[tid], &sm.szv[tid], &sm.czv[tid]);
    if (tid < SP) sm.rcnt[tid] = 0;
    if (tid == 0) {
        sm.sEtaR = gEtaR[0]; sm.sEtaA = gEtaA[0]; sm.sZeta = gZeta[0]; sm.nn = 0;
    }
    __syncthreads();

    // ---- phase 1: distances from center i; compact radial + angular ----
    if (tid < AT && tid != i) {
        const float* cj = coords + (size_t)(m * AT + tid) * 3;
        const float* ci = coords + (size_t)(m * AT + i) * 3;   // broadcast, cached
        float dx = cj[0] - ci[0];
        float dy = cj[1] - ci[1];
        float dz = cj[2] - ci[2];
        float d  = sqrtf(dx * dx + dy * dy + dz * dz);
        int sp_  = species[m * AT + tid];
        if (d <= RCRf) {
            float fc = 0.5f * __cosf(d * (PI_F / RCRf)) + 0.5f;
            int s = atomicAdd(&sm.rcnt[sp_], 1);
            sm.rbdf[sp_ * AT + s] = make_float2(d, 0.25f * fc);
        }
        if (d <= RCAf) {
            int s = atomicAdd(&sm.nn, 1);
            sm.adx[s] = dx; sm.ady[s] = dy; sm.adz[s] = dz;
            sm.ad[s]  = d;
            sm.ard[s] = 1.0f / fmaxf(d, 1e-8f);
            sm.afc[s] = 0.5f * __cosf(d * (PI_F / RCAf)) + 0.5f;
            sm.asp[s] = sp_;
        }
    }
    __syncthreads();

    const int n  = sm.nn;
    const int np = (n * (n - 1)) >> 1;
    const float etaR = sm.sEtaR, etaA = sm.sEtaA, zeta = sm.sZeta;
    const bool z32 = (zeta == 32.0f);

    // ---- per-thread output ownership: o = tid, tid+NT, tid+2*NT ----
    // slot 0 is radial for tid < 64, angular otherwise; slots 1,2 always angular.
    float acc0 = 0.0f, acc1 = 0.0f, acc2 = 0.0f;

    // angular constants per slot (pidx warp-uniform in every slot)
    int   px0 = -1, px1, px2;
    float cz0 = 0, sz0 = 0, sh0 = 0, cz1, sz1, sh1, cz2, sz2, sh2;
    {
        int o0 = tid;
        if (o0 >= RADSUB) {
            int own = o0 - RADSUB;
            px0 = own >> 5; int rr = own & 31;
            cz0 = sm.czv[rr & 7]; sz0 = sm.szv[rr & 7]; sh0 = sm.shfA[rr >> 3];
        }
        int own1 = tid + NT - RADSUB;
        px1 = own1 >> 5; int r1 = own1 & 31;
        cz1 = sm.czv[r1 & 7]; sz1 = sm.szv[r1 & 7]; sh1 = sm.shfA[r1 >> 3];
        int own2 = tid + 2 * NT - RADSUB;
        px2 = own2 >> 5; int r2 = own2 & 31;
        cz2 = sm.czv[r2 & 7]; sz2 = sm.szv[r2 & 7]; sh2 = sm.shfA[r2 >> 3];
    }

    // ---- radial gather (independent of pair chunks) ----
    if (tid < RADSUB) {
        const int spb = tid >> 4;
        const float sh = sm.shfR[tid & 15];
        const int cnt = sm.rcnt[spb];
        const float2* b = sm.rbdf + spb * AT;
        for (int j = 0; j < cnt; j++) {
            float2 df = b[j];
            float t = df.x - sh;
            acc0 = fmaf(df.y, __expf(-etaR * t * t), acc0);
        }
    }

    // ---- chunked angular pipeline ----
    for (int base = 0; base < np; base += NPCAP) {
        const int pe = min(np, base + NPCAP);
        __syncthreads();                       // prior chunk's gather done
        if (tid < NPAIRS_SP) sm.acnt[tid] = 0;
        __syncthreads();

        // phase 2: per-pair precompute + bucket counts
        for (int p = base + tid; p < pe; p += NT) {
            // decode p -> (j < k); pairs before row j: j*(2n-1-j)/2
            float fn = (float)(2 * n - 1);
            int j = (int)((fn - sqrtf(fn * fn - 8.0f * (float)p)) * 0.5f);
            if (j < 0) j = 0;
            if (j > n - 2) j = n - 2;
            while (j > 0 && (j * (2 * n - 1 - j)) / 2 > p) j--;
            while (((j + 1) * (2 * n - 2 - j)) / 2 <= p) j++;
            int k = p - (j * (2 * n - 1 - j)) / 2 + j + 1;

            float dot  = sm.adx[j] * sm.adx[k] + sm.ady[j] * sm.ady[k] + sm.adz[j] * sm.adz[k];
            float cosv = 0.95f * dot * sm.ard[j] * sm.ard[k];
            float sinv = sqrtf(fmaxf(1.0f - cosv * cosv, 0.0f));
            float fcj2 = 2.0f * sm.afc[j] * sm.afc[k];
            float dm   = 0.5f * (sm.ad[j] + sm.ad[k]);
            int lp = p - base;
            sm.pdata[lp] = make_float4(cosv, sinv, fcj2, dm);

            int sa = sm.asp[j], sb = sm.asp[k];
            int lo = min(sa, sb), hi = max(sa, sb);
            int px = lo * SP - (lo * (lo - 1)) / 2 + (hi - lo);
            sm.ppx[lp] = (unsigned char)px;
            atomicAdd(&sm.acnt[px], 1);
        }
        __syncthreads();

        if (tid == 0) {
            int run = 0;
            #pragma unroll
            for (int q = 0; q < NPAIRS_SP; q++) {
                sm.abase[q] = run;
                sm.afill[q] = run;
                run += sm.acnt[q];
            }
        }
        __syncthreads();

        // phase 3: scatter sorted indices
        for (int lp = tid; lp < pe - base; lp += NT) {
            int dst = atomicAdd(&sm.afill[sm.ppx[lp]], 1);
            sm.ord[dst] = (unsigned short)lp;
        }
        __syncthreads();

        // phase 4: angular gather accumulate for this chunk
        if (px0 >= 0) acc0 = ang_accum(&sm, acc0, px0, cz0, sz0, sh0, etaA, zeta, z32);
        acc1 = ang_accum(&sm, acc1, px1, cz1, sz1, sh1, etaA, zeta, z32);
        acc2 = ang_accum(&sm, acc2, px2, cz2, sz2, sh2, etaA, zeta, z32);
    }

    // ---- write out ----
    float* o = out + ((size_t)m * AT + i) * OUTW;
    o[tid]          = acc0;
    o[tid + NT]     = acc1;
    o[tid + 2 * NT] = acc2;
}

extern "C" void kernel_launch(void* const* d_in, const int* in_sizes, int n_in,
                              void* d_out, int out_size) {
    const float* coords = (const float*)d_in[0];
    const float* EtaR   = (const float*)d_in[1];
    const float* ShfR   = (const float*)d_in[2];
    const float* EtaA   = (const float*)d_in[3];
    const float* Zeta   = (const float*)d_in[4];
    const float* ShfA   = (const float*)d_in[5];
    const float* ShfZ   = (const float*)d_in[6];
    const int*   sp     = (const int*)d_in[7];
    float* out = (float*)d_out;

    const int M = in_sizes[0] / (AT * 3);
    dim3 grid(AT, M);
    aev_kernel<<<grid, NT>>>(coords, EtaR, ShfR, EtaA, Zeta, ShfA, ShfZ, sp, out);
}